// round 5
// baseline (speedup 1.0000x reference)
#include <cuda_runtime.h>
#include <cuda_bf16.h>

#define NN    50000
#define DIN   128
#define HH    64
#define CC    2
#define EMAX  800000
#define NB    ((NN + 255) / 256)   // 196 scan blocks

// ---------------- scratch (static __device__, no allocation) ----------------
__device__ int d_flag64;
__device__ __align__(16) int   d_cnt[NN];
__device__ __align__(16) int   d_rp [NN + 1];
__device__ __align__(16) int   d_cur[NN];
__device__ __align__(16) int   d_bsum[NB];
__device__ __align__(16) int   d_boff[NB];
__device__ __align__(16) int   d_col[EMAX];
__device__ __align__(16) float d_dinv[NN];
__device__ __align__(16) float d_g1[(size_t)NN * HH];   // (x@W1)*dinv[src]
__device__ __align__(16) float d_g2[NN * CC];           // layer-2 pre-scatter msgs

__device__ __forceinline__ int edge_at(const void* p, long long i) {
    if (d_flag64) return (int)((const long long*)p)[i];
    return ((const int*)p)[i];
}

// packed fp32x2 fma (Blackwell FFMA2)
__device__ __forceinline__ unsigned long long ffma2(unsigned long long a,
                                                    unsigned long long b,
                                                    unsigned long long c) {
    unsigned long long d;
    asm("fma.rn.f32x2 %0, %1, %2, %3;" : "=l"(d) : "l"(a), "l"(b), "l"(c));
    return d;
}
__device__ __forceinline__ float f2sum(unsigned long long a) {
    return __uint_as_float((unsigned)a) + __uint_as_float((unsigned)(a >> 32));
}

// ------------- init: zero counts; block 0 also probes int64/int32 -----------
__global__ void k_init(const int* __restrict__ p) {
    int i = blockIdx.x * blockDim.x + threadIdx.x;
    if (i < NN) d_cnt[i] = 0;
    if (blockIdx.x == 0) {
        __shared__ int ok;
        if (threadIdx.x == 0) ok = 1;
        __syncthreads();
        int bad = 0;
        for (int s = threadIdx.x; s < 1024; s += blockDim.x) {
            int lo = p[2 * s], hi = p[2 * s + 1];
            if (hi != 0 || lo < 0 || lo >= NN) bad = 1;
        }
        if (bad) atomicAnd(&ok, 0);
        __syncthreads();
        if (threadIdx.x == 0) d_flag64 = ok;
    }
}

// count in-degree (dst half only)
__global__ void k_count(const void* __restrict__ p, int E) {
    int i = blockIdx.x * blockDim.x + threadIdx.x;
    if (i >= E) return;
    int d = edge_at(p, (long long)E + i);
    atomicAdd(&d_cnt[d], 1);
}

// ---------------- two-level scan --------------------------------------------
__global__ void __launch_bounds__(256) k_scan1() {
    __shared__ int sm[256];
    const int tid = threadIdx.x;
    const int i   = blockIdx.x * 256 + tid;
    int v = (i < NN) ? d_cnt[i] : 0;
    sm[tid] = v;
    __syncthreads();
    #pragma unroll
    for (int off = 1; off < 256; off <<= 1) {
        int t = (tid >= off) ? sm[tid - off] : 0;
        __syncthreads();
        sm[tid] += t;
        __syncthreads();
    }
    if (i < NN) d_rp[i] = sm[tid] - v;          // exclusive, block-local
    if (tid == 255) d_bsum[blockIdx.x] = sm[255];
}

__global__ void __launch_bounds__(256) k_scan2() {
    __shared__ int sm[256];
    const int tid = threadIdx.x;
    int v = (tid < NB) ? d_bsum[tid] : 0;
    sm[tid] = v;
    __syncthreads();
    #pragma unroll
    for (int off = 1; off < 256; off <<= 1) {
        int t = (tid >= off) ? sm[tid - off] : 0;
        __syncthreads();
        sm[tid] += t;
        __syncthreads();
    }
    if (tid < NB) d_boff[tid] = sm[tid] - v;
    if (tid == NB - 1) d_rp[NN] = sm[tid];
}

__global__ void __launch_bounds__(256) k_scan3() {
    const int i = blockIdx.x * 256 + threadIdx.x;
    if (i >= NN) return;
    int r = d_rp[i] + d_boff[blockIdx.x];
    d_rp[i]  = r;
    d_cur[i] = r;
    d_dinv[i] = rsqrtf((float)(1 + d_cnt[i]));
}

// fill CSR col array (order nondeterministic; sum tolerance covers it)
__global__ void k_bucket(const void* __restrict__ p, int E) {
    int e = blockIdx.x * blockDim.x + threadIdx.x;
    if (e >= E) return;
    int s = edge_at(p, e);
    int d = edge_at(p, (long long)E + e);
    int pos = atomicAdd(&d_cur[d], 1);
    d_col[pos] = s;
}

// ---------------- layer 1 GEMM: g1 = (x @ W1) * dinv ------------------------
// 128 nodes x 64 outs tile, 256 threads, FFMA2 packed along K (even/odd lanes)
// thread (tx=tid&15, ty=tid>>4): nodes ty*8..ty*8+7, cols 4*tx..4*tx+3
#define XP 34   // xs row pitch (floats): 8B-aligned, bank-safe
#define WP 34   // Ws_t row pitch
__global__ void __launch_bounds__(256, 2) k_gemm1(const float* __restrict__ x,
                                                  const float* __restrict__ W1) {
    __shared__ float xs[128 * XP];   // node-major tile, 32 k per chunk
    __shared__ float Ws[64 * WP];    // transposed W chunk: [col][k]
    const int tid = threadIdx.x;
    const int tx = tid & 15;
    const int ty = tid >> 4;
    const int nb = blockIdx.x * 128;

    unsigned long long acc[8][4];
    #pragma unroll
    for (int j = 0; j < 8; j++)
        #pragma unroll
        for (int c = 0; c < 4; c++) acc[j][c] = 0ULL;

    for (int kk = 0; kk < DIN; kk += 32) {
        __syncthreads();
        // stage W1 rows kk..kk+31 TRANSPOSED: Ws[col*WP + k] = W1[kk+k][col]
        for (int i = tid; i < 512; i += 256) {      // 512 float4 = 2048 floats
            int r = i >> 4, c4 = i & 15;
            float4 w = ((const float4*)(W1 + (size_t)(kk + r) * HH))[c4];
            Ws[(4 * c4 + 0) * WP + r] = w.x;
            Ws[(4 * c4 + 1) * WP + r] = w.y;
            Ws[(4 * c4 + 2) * WP + r] = w.z;
            Ws[(4 * c4 + 3) * WP + r] = w.w;
        }
        // stage x tile node-major: 128 nodes x 32 floats, float2 granularity
        for (int i = tid; i < 2048; i += 256) {
            int r = i >> 4, c2 = i & 15;
            int node = nb + r;
            float2 v = make_float2(0.f, 0.f);
            if (node < NN)
                v = *(const float2*)(x + (size_t)node * DIN + kk + 2 * c2);
            *(float2*)(xs + r * XP + 2 * c2) = v;
        }
        __syncthreads();

        #pragma unroll 4
        for (int k2 = 0; k2 < 16; k2++) {
            unsigned long long xv[8];
            #pragma unroll
            for (int j = 0; j < 8; j++)
                xv[j] = *(const unsigned long long*)(xs + (ty * 8 + j) * XP + 2 * k2);
            #pragma unroll
            for (int c = 0; c < 4; c++) {
                unsigned long long wv =
                    *(const unsigned long long*)(Ws + (4 * tx + c) * WP + 2 * k2);
                #pragma unroll
                for (int j = 0; j < 8; j++)
                    acc[j][c] = ffma2(xv[j], wv, acc[j][c]);
            }
        }
    }

    #pragma unroll
    for (int j = 0; j < 8; j++) {
        int node = nb + ty * 8 + j;
        if (node < NN) {
            float di = d_dinv[node];
            float4 v = make_float4(f2sum(acc[j][0]) * di, f2sum(acc[j][1]) * di,
                                   f2sum(acc[j][2]) * di, f2sum(acc[j][3]) * di);
            ((float4*)(d_g1 + (size_t)node * HH))[tx] = v;
        }
    }
}

// ------- fused: aggregate layer1 (gather) + relu/bias + GEMM2 + scale -------
// warp per node: lane holds cols [2*lane, 2*lane+1]
__global__ void __launch_bounds__(256) k_agg1(const float* __restrict__ b1,
                                              const float* __restrict__ W2) {
    __shared__ float w2s[HH * CC];
    __shared__ float b1s[HH];
    const int tid = threadIdx.x;
    if (tid < HH * CC) w2s[tid] = W2[tid];
    if (tid < HH)      b1s[tid] = b1[tid];
    __syncthreads();

    const int warp = tid >> 5, lane = tid & 31;
    const int node = blockIdx.x * 8 + warp;
    if (node >= NN) return;

    const float2* __restrict__ g1v = (const float2*)d_g1;
    float2 acc = g1v[(size_t)node * 32 + lane];   // self-loop term

    const int rs = d_rp[node], re = d_rp[node + 1];
    int k = rs;
    for (; k + 3 < re; k += 4) {
        int s0 = d_col[k], s1 = d_col[k + 1], s2 = d_col[k + 2], s3 = d_col[k + 3];
        float2 v0 = g1v[(size_t)s0 * 32 + lane];
        float2 v1 = g1v[(size_t)s1 * 32 + lane];
        float2 v2 = g1v[(size_t)s2 * 32 + lane];
        float2 v3 = g1v[(size_t)s3 * 32 + lane];
        acc.x += (v0.x + v1.x) + (v2.x + v3.x);
        acc.y += (v0.y + v1.y) + (v2.y + v3.y);
    }
    for (; k < re; k++) {
        float2 v = g1v[(size_t)d_col[k] * 32 + lane];
        acc.x += v.x; acc.y += v.y;
    }

    const float di = d_dinv[node];
    float h0 = fmaxf(fmaf(di, acc.x, b1s[2 * lane    ]), 0.0f);
    float h1 = fmaxf(fmaf(di, acc.y, b1s[2 * lane + 1]), 0.0f);
    float a0 = h0 * w2s[4 * lane + 0] + h1 * w2s[4 * lane + 2];
    float a1 = h0 * w2s[4 * lane + 1] + h1 * w2s[4 * lane + 3];
    #pragma unroll
    for (int off = 16; off; off >>= 1) {
        a0 += __shfl_xor_sync(0xffffffff, a0, off);
        a1 += __shfl_xor_sync(0xffffffff, a1, off);
    }
    if (lane == 0)
        *(float2*)(d_g2 + node * CC) = make_float2(a0 * di, a1 * di);
}

// ---------- layer 2 aggregate (gather) + bias -> out, thread per node -------
__global__ void k_agg2(float* __restrict__ out, const float* __restrict__ b2) {
    int i = blockIdx.x * blockDim.x + threadIdx.x;
    if (i >= NN) return;
    const float2* __restrict__ g2v = (const float2*)d_g2;
    float2 acc = g2v[i];   // self-loop
    const int rs = d_rp[i], re = d_rp[i + 1];
    int k = rs;
    for (; k + 3 < re; k += 4) {
        int s0 = d_col[k], s1 = d_col[k + 1], s2 = d_col[k + 2], s3 = d_col[k + 3];
        float2 v0 = g2v[s0], v1 = g2v[s1], v2 = g2v[s2], v3 = g2v[s3];
        acc.x += (v0.x + v1.x) + (v2.x + v3.x);
        acc.y += (v0.y + v1.y) + (v2.y + v3.y);
    }
    for (; k < re; k++) {
        float2 v = g2v[d_col[k]];
        acc.x += v.x; acc.y += v.y;
    }
    const float di = d_dinv[i];
    *(float2*)(out + i * CC) =
        make_float2(fmaf(di, acc.x, b2[0]), fmaf(di, acc.y, b2[1]));
}

// ---------------- launch ----------------------------------------------------
extern "C" void kernel_launch(void* const* d_in, const int* in_sizes, int n_in,
                              void* d_out, int out_size) {
    const float* x  = (const float*)d_in[0];
    const void*  ei = d_in[1];
    const float* W1 = (const float*)d_in[2];
    const float* b1 = (const float*)d_in[3];
    const float* W2 = (const float*)d_in[4];
    const float* b2 = (const float*)d_in[5];
    float* out = (float*)d_out;

    const int E = in_sizes[1] / 2;

    k_init  <<<NB, 256>>>((const int*)ei);
    k_count <<<(E + 255) / 256, 256>>>(ei, E);
    k_scan1 <<<NB, 256>>>();
    k_scan2 <<<1, 256>>>();
    k_scan3 <<<NB, 256>>>();
    k_bucket<<<(E + 255) / 256, 256>>>(ei, E);
    k_gemm1 <<<(NN + 127) / 128, 256>>>(x, W1);
    k_agg1  <<<(NN + 7) / 8, 256>>>(b1, W2);
    k_agg2  <<<(NN + 255) / 256, 256>>>(out, b2);
}

// round 6
// speedup vs baseline: 1.1014x; 1.1014x over previous
#include <cuda_runtime.h>
#include <cuda_bf16.h>

#define NN    50000
#define DIN   128
#define HH    64
#define CC    2
#define EMAX  800000
#define G     148          // persistent grid: one block per SM
#define CH    ((NN + G - 1) / G)   // 338 nodes per block in scan

// ---------------- scratch (static __device__, no allocation) ----------------
__device__ int d_flag64;
__device__ __align__(16) int   d_cnt[NN];
__device__ __align__(16) int   d_rp [NN + 1];
__device__ __align__(16) int   d_cur[NN];
__device__ __align__(16) int   d_bsum[G];
__device__ __align__(16) int   d_boff[G];
__device__ __align__(16) int   d_col[EMAX];
__device__ __align__(16) float d_dinv[NN];
__device__ __align__(16) float d_g1[(size_t)NN * HH];   // (x@W1)*dinv[src]
__device__ __align__(16) float d_g2[NN * CC];           // layer-2 pre-scatter msgs

// software grid barrier state (monotonic generation -> replay-safe)
__device__ unsigned g_barcnt = 0;
__device__ unsigned g_bargen = 0;

__device__ __forceinline__ void gbar() {
    __syncthreads();
    if (threadIdx.x == 0) {
        __threadfence();
        unsigned gen = *(volatile unsigned*)&g_bargen;
        unsigned arr = atomicAdd(&g_barcnt, 1u);
        if (arr == G - 1) {
            g_barcnt = 0;
            __threadfence();
            atomicAdd(&g_bargen, 1u);
        } else {
            while (*(volatile unsigned*)&g_bargen == gen) { }
        }
        __threadfence();
    }
    __syncthreads();
}

__device__ __forceinline__ int edge_at(const void* p, long long i) {
    if (d_flag64) return (int)((const long long*)p)[i];
    return ((const int*)p)[i];
}

// ---------------- fused preprocess: detect+zero+count+scan+bucket -----------
__global__ void __launch_bounds__(256) k_preprocess(const void* __restrict__ ei,
                                                    int E) {
    __shared__ int sm[256];
    const int tid = threadIdx.x;
    const int b   = blockIdx.x;

    // Phase A: zero counts; block 0 probes dtype
    for (int i = b * 256 + tid; i < NN; i += G * 256) d_cnt[i] = 0;
    if (b == 0) {
        const int* p = (const int*)ei;
        __shared__ int ok;
        if (tid == 0) ok = 1;
        __syncthreads();
        int bad = 0;
        for (int s = tid; s < 1024; s += 256) {
            int lo = p[2 * s], hi = p[2 * s + 1];
            if (hi != 0 || lo < 0 || lo >= NN) bad = 1;
        }
        if (bad) atomicAnd(&ok, 0);
        __syncthreads();
        if (tid == 0) d_flag64 = ok;
    }
    gbar();

    // Phase B: count in-degree (dst half)
    for (int i = b * 256 + tid; i < E; i += G * 256) {
        int d = edge_at(ei, (long long)E + i);
        atomicAdd(&d_cnt[d], 1);
    }
    gbar();

    // Phase C1: per-block scan of chunk [b*CH, b*CH+CH)
    {
        const int base = b * CH;
        const int end  = min(base + CH, NN);
        const int t0   = base + tid * 2;
        int c0 = (t0     < end) ? d_cnt[t0]     : 0;
        int c1 = (t0 + 1 < end) ? d_cnt[t0 + 1] : 0;
        int v = c0 + c1;
        sm[tid] = v;
        __syncthreads();
        #pragma unroll
        for (int off = 1; off < 256; off <<= 1) {
            int t = (tid >= off) ? sm[tid - off] : 0;
            __syncthreads();
            sm[tid] += t;
            __syncthreads();
        }
        int excl = sm[tid] - v;
        if (t0     < end) d_rp[t0]     = excl;
        if (t0 + 1 < end) d_rp[t0 + 1] = excl + c0;
        if (tid == 255) d_bsum[b] = sm[255];
    }
    gbar();

    // Phase C2: block 0 scans the G block sums
    if (b == 0) {
        int v = (tid < G) ? d_bsum[tid] : 0;
        sm[tid] = v;
        __syncthreads();
        #pragma unroll
        for (int off = 1; off < 256; off <<= 1) {
            int t = (tid >= off) ? sm[tid - off] : 0;
            __syncthreads();
            sm[tid] += t;
            __syncthreads();
        }
        if (tid < G) d_boff[tid] = sm[tid] - v;
        if (tid == G - 1) d_rp[NN] = sm[tid];
    }
    gbar();

    // Phase C3: add block offset; init cursor; dinv
    {
        const int base = b * CH;
        const int end  = min(base + CH, NN);
        const int off  = d_boff[b];
        for (int i = base + tid; i < end; i += 256) {
            int r = d_rp[i] + off;
            d_rp[i]  = r;
            d_cur[i] = r;
            d_dinv[i] = rsqrtf((float)(1 + d_cnt[i]));
        }
    }
    gbar();

    // Phase D: bucket edges into CSR
    for (int e = b * 256 + tid; e < E; e += G * 256) {
        int s = edge_at(ei, e);
        int d = edge_at(ei, (long long)E + e);
        int pos = atomicAdd(&d_cur[d], 1);
        d_col[pos] = s;
    }
}

// ---------------- layer 1 GEMM: g1 = (x @ W1) * dinv ------------------------
// tile 128 nodes x 64 outs, 256 threads, 8x4 micro-tile (proven round-4 tiling)
__global__ void __launch_bounds__(256) k_gemm1(const float* __restrict__ x,
                                               const float* __restrict__ W1) {
    __shared__ float xs[128][64];   // 32 KB
    __shared__ float Ws[64][64];    // 16 KB
    const int tid = threadIdx.x;
    const int tx = tid & 15;        // out group: o = 4*tx
    const int ty = tid >> 4;        // node group: n = ty*8 + j
    const int nb = blockIdx.x * 128;

    float acc[8][4];
    #pragma unroll
    for (int j = 0; j < 8; j++)
        #pragma unroll
        for (int c = 0; c < 4; c++) acc[j][c] = 0.0f;

    for (int kk = 0; kk < DIN; kk += 64) {
        __syncthreads();
        for (int i = tid; i < 1024; i += 256) {
            int r = i >> 4, c4 = i & 15;
            ((float4*)Ws[r])[c4] = ((const float4*)(W1 + (size_t)(kk + r) * HH))[c4];
        }
        for (int i = tid; i < 2048; i += 256) {
            int r = i >> 4, c4 = i & 15;
            int node = nb + r;
            float4 v = make_float4(0.f, 0.f, 0.f, 0.f);
            if (node < NN) v = ((const float4*)(x + (size_t)node * DIN + kk))[c4];
            ((float4*)xs[r])[c4] = v;
        }
        __syncthreads();

        #pragma unroll 8
        for (int k = 0; k < 64; k++) {
            float4 w = ((float4*)Ws[k])[tx];
            #pragma unroll
            for (int j = 0; j < 8; j++) {
                float xv = xs[ty * 8 + j][k];
                acc[j][0] = fmaf(xv, w.x, acc[j][0]);
                acc[j][1] = fmaf(xv, w.y, acc[j][1]);
                acc[j][2] = fmaf(xv, w.z, acc[j][2]);
                acc[j][3] = fmaf(xv, w.w, acc[j][3]);
            }
        }
    }

    #pragma unroll
    for (int j = 0; j < 8; j++) {
        int node = nb + ty * 8 + j;
        if (node < NN) {
            float di = d_dinv[node];
            float4 v = make_float4(acc[j][0] * di, acc[j][1] * di,
                                   acc[j][2] * di, acc[j][3] * di);
            ((float4*)(d_g1 + (size_t)node * HH))[tx] = v;
        }
    }
}

// ------- fused: aggregate layer1 (gather) + relu/bias + GEMM2 + scale -------
// warp per node: lane holds cols [2*lane, 2*lane+1]
__global__ void __launch_bounds__(256) k_agg1(const float* __restrict__ b1,
                                              const float* __restrict__ W2) {
    __shared__ float w2s[HH * CC];
    __shared__ float b1s[HH];
    const int tid = threadIdx.x;
    if (tid < HH * CC) w2s[tid] = W2[tid];
    if (tid < HH)      b1s[tid] = b1[tid];
    __syncthreads();

    const int warp = tid >> 5, lane = tid & 31;
    const int node = blockIdx.x * 8 + warp;
    if (node >= NN) return;

    const float2* __restrict__ g1v = (const float2*)d_g1;
    float2 acc = g1v[(size_t)node * 32 + lane];   // self-loop term

    const int rs = d_rp[node], re = d_rp[node + 1];
    int k = rs;
    for (; k + 3 < re; k += 4) {
        int s0 = d_col[k], s1 = d_col[k + 1], s2 = d_col[k + 2], s3 = d_col[k + 3];
        float2 v0 = g1v[(size_t)s0 * 32 + lane];
        float2 v1 = g1v[(size_t)s1 * 32 + lane];
        float2 v2 = g1v[(size_t)s2 * 32 + lane];
        float2 v3 = g1v[(size_t)s3 * 32 + lane];
        acc.x += (v0.x + v1.x) + (v2.x + v3.x);
        acc.y += (v0.y + v1.y) + (v2.y + v3.y);
    }
    for (; k < re; k++) {
        float2 v = g1v[(size_t)d_col[k] * 32 + lane];
        acc.x += v.x; acc.y += v.y;
    }

    const float di = d_dinv[node];
    float h0 = fmaxf(fmaf(di, acc.x, b1s[2 * lane    ]), 0.0f);
    float h1 = fmaxf(fmaf(di, acc.y, b1s[2 * lane + 1]), 0.0f);
    float a0 = h0 * w2s[4 * lane + 0] + h1 * w2s[4 * lane + 2];
    float a1 = h0 * w2s[4 * lane + 1] + h1 * w2s[4 * lane + 3];
    #pragma unroll
    for (int off = 16; off; off >>= 1) {
        a0 += __shfl_xor_sync(0xffffffff, a0, off);
        a1 += __shfl_xor_sync(0xffffffff, a1, off);
    }
    if (lane == 0)
        *(float2*)(d_g2 + node * CC) = make_float2(a0 * di, a1 * di);
}

// ---------- layer 2 aggregate (gather) + bias -> out, thread per node -------
__global__ void k_agg2(float* __restrict__ out, const float* __restrict__ b2) {
    int i = blockIdx.x * blockDim.x + threadIdx.x;
    if (i >= NN) return;
    const float2* __restrict__ g2v = (const float2*)d_g2;
    float2 acc = g2v[i];   // self-loop
    const int rs = d_rp[i], re = d_rp[i + 1];
    int k = rs;
    for (; k + 3 < re; k += 4) {
        int s0 = d_col[k], s1 = d_col[k + 1], s2 = d_col[k + 2], s3 = d_col[k + 3];
        float2 v0 = g2v[s0], v1 = g2v[s1], v2 = g2v[s2], v3 = g2v[s3];
        acc.x += (v0.x + v1.x) + (v2.x + v3.x);
        acc.y += (v0.y + v1.y) + (v2.y + v3.y);
    }
    for (; k < re; k++) {
        float2 v = g2v[d_col[k]];
        acc.x += v.x; acc.y += v.y;
    }
    const float di = d_dinv[i];
    *(float2*)(out + i * CC) =
        make_float2(fmaf(di, acc.x, b2[0]), fmaf(di, acc.y, b2[1]));
}

// ---------------- launch ----------------------------------------------------
extern "C" void kernel_launch(void* const* d_in, const int* in_sizes, int n_in,
                              void* d_out, int out_size) {
    const float* x  = (const float*)d_in[0];
    const void*  ei = d_in[1];
    const float* W1 = (const float*)d_in[2];
    const float* b1 = (const float*)d_in[3];
    const float* W2 = (const float*)d_in[4];
    const float* b2 = (const float*)d_in[5];
    float* out = (float*)d_out;

    const int E = in_sizes[1] / 2;

    k_preprocess<<<G, 256>>>(ei, E);
    k_gemm1 <<<(NN + 127) / 128, 256>>>(x, W1);
    k_agg1  <<<(NN + 7) / 8, 256>>>(b1, W2);
    k_agg2  <<<(NN + 255) / 256, 256>>>(out, b2);
}